// round 16
// baseline (speedup 1.0000x reference)
#include <cuda_runtime.h>
#include <cuda_fp16.h>
#include <cstdint>

// MeanShift: B=2, C=3, N=9216, 5 iters.
// w_ij = exp2( (2g*y_i).x_j - g||x_j||^2 - g||y_i||^2 ), g = 50/ln2.
// HMMA accumulation (m16n8k16 f16xf16+f32) + precomputed fp16 B-frag table.
// R16 = R14 + hybrid exp: 2 of the 8 exps per warp-window move from MUFU
// (ex2.approx.f16x2, suspected dual-pass rt16) to an FMA-pipe cubic-poly
// exp2 in packed f32x2 (range-reduce + poly + integer exponent insert).
// 768 thr = 4 query-pairs x 6 j-splits, psum overlays points region.

#define NPTS 9216
#define NB 2
#define GG 72.13475204444817f
#define TPB 768
#define NJS 6
#define WINS_PER_JS 96
#define NWINT 576

typedef unsigned long long u64;
typedef unsigned int u32;

__device__ float4 g_pts[NB * NPTS];
__device__ float4 g_y[2][NB * NPTS];
__device__ __align__(16) unsigned char g_feat[NB * NWINT * 128];

#define SO_FEAT 147456
#define SMEMSZ  221184

static __device__ __forceinline__ u64 pk2(float a, float b) {
    u64 r; asm("mov.b64 %0,{%1,%2};" : "=l"(r) : "f"(a), "f"(b)); return r;
}
static __device__ __forceinline__ u64 fma2(u64 a, u64 b, u64 c) {
    u64 d; asm("fma.rn.f32x2 %0,%1,%2,%3;" : "=l"(d) : "l"(a), "l"(b), "l"(c)); return d;
}
static __device__ __forceinline__ u64 add2(u64 a, u64 b) {
    u64 d; asm("add.rn.f32x2 %0,%1,%2;" : "=l"(d) : "l"(a), "l"(b)); return d;
}
static __device__ __forceinline__ u64 mul2(u64 a, u64 b) {
    u64 d; asm("mul.rn.f32x2 %0,%1,%2;" : "=l"(d) : "l"(a), "l"(b)); return d;
}
static __device__ __forceinline__ void lds2(u32 a, u64& x, u64& y) {
    asm volatile("ld.shared.v2.u64 {%0,%1},[%2];" : "=l"(x), "=l"(y) : "r"(a));
}
static __device__ __forceinline__ u32 lds32(u32 a) {
    u32 v; asm volatile("ld.shared.b32 %0,[%1];" : "=r"(v) : "r"(a)); return v;
}
// MUFU path: f32x2 arg -> fp16x2 weights via cvt + ex2.approx.f16x2.
static __device__ __forceinline__ u32 wgt2(u64 t) {
    u32 h;
    asm("{\n\t.reg .f32 lo,hi;\n\tmov.b64 {lo,hi},%1;\n\t"
        "cvt.rn.f16x2.f32 %0,hi,lo;\n\tex2.approx.f16x2 %0,%0;\n\t}" : "=r"(h) : "l"(t));
    return h;
}
// FMA-pipe path: 2^t per lane via cubic minimax + exponent reinsert.
// MAG=2^23*1.5; clamp k>=-30 (smaller weights flush to 0 in fp16 anyway).
#define PMAG  0x4B4000004B400000ull
#define PNMAG 0xCB400000CB400000ull
#define PN1   0xBF800000BF800000ull
static __device__ __forceinline__ u32 wgt2p(u64 t, u64 C3, u64 C2, u64 C1, u64 C0) {
    u64 m = add2(t, PMAG);                 // RN -> k in low mantissa bits
    u64 r = add2(m, PNMAG);                // r = round(t)
    u64 f = fma2(r, PN1, t);               // f = t - r, in [-0.5, 0.5]
    u64 p = fma2(f, C3, C2);
    p = fma2(f, p, C1);
    p = fma2(f, p, C0);                    // 2^f
    u32 mlo = (u32)m, mhi = (u32)(m >> 32);
    mlo = mlo > 0x4B3FFFE2u ? mlo : 0x4B3FFFE2u;   // k >= -30
    mhi = mhi > 0x4B3FFFE2u ? mhi : 0x4B3FFFE2u;
    u32 slo = (mlo + 0xB4C0007Fu) << 23;   // bits of 2^k
    u32 shi = (mhi + 0xB4C0007Fu) << 23;
    u64 w = mul2(p, ((u64)shi << 32) | (u64)slo);
    u32 h;
    asm("{\n\t.reg .f32 lo,hi;\n\tmov.b64 {lo,hi},%1;\n\tcvt.rn.f16x2.f32 %0,hi,lo;\n\t}"
        : "=r"(h) : "l"(w));
    return h;
}
static __device__ __forceinline__ void mma16816(
    float& c0, float& c1, float& c2, float& c3,
    u32 a0, u32 a1, u32 a2, u32 a3, u32 b0, u32 b1) {
    asm volatile("mma.sync.aligned.m16n8k16.row.col.f32.f16.f16.f32 "
        "{%0,%1,%2,%3}, {%4,%5,%6,%7}, {%8,%9}, {%0,%1,%2,%3};"
        : "+f"(c0), "+f"(c1), "+f"(c2), "+f"(c3)
        : "r"(a0), "r"(a1), "r"(a2), "r"(a3), "r"(b0), "r"(b1));
}

__global__ void prep_kernel(const float* __restrict__ x) {
    int idx = blockIdx.x * blockDim.x + threadIdx.x;
    if (idx >= NB * NPTS) return;
    int b = idx / NPTS, n = idx - b * NPTS;
    float px = x[(b * 3 + 0) * NPTS + n];
    float py = x[(b * 3 + 1) * NPTS + n];
    float pz = x[(b * 3 + 2) * NPTS + n];
    float bn = -GG * (px * px + py * py + pz * pz);
    int jp = n >> 1, l = n & 1;
    float* base = (float*)&g_pts[b * NPTS + 2 * jp];
    base[0 + l] = px; base[2 + l] = py; base[4 + l] = pz; base[6 + l] = bn;
    g_y[0][b * NPTS + n] = make_float4(px, py, pz, 0.f);

    int i = n & 15;
    unsigned char* fb = g_feat + ((size_t)(b * NWINT + (n >> 4))) * 128
                      + (i >> 1) * 4 + (i & 1) * 2;
    *(__half*)(fb + 0)  = __float2half(px);
    *(__half*)(fb + 32) = __float2half(py);
    *(__half*)(fb + 64) = __float2half(pz);
    *(__half*)(fb + 96) = __float2half(1.0f);
}

__global__ __launch_bounds__(TPB, 1) void iter_kernel(int src, int dst, float* __restrict__ out) {
    extern __shared__ __align__(16) unsigned char smem[];
    const int tid = threadIdx.x, wid = tid >> 5, lane = tid & 31;
    const int g = lane >> 2, t = lane & 3;
    const int b = blockIdx.y, tile = blockIdx.x;
    u32 sb = (u32)__cvta_generic_to_shared(smem);

    {   // stage points (147456 B) + feature table (73728 B)
        const float4* gp = g_pts + b * NPTS;
        float4* sp = (float4*)smem;
        for (int i = tid; i < NPTS; i += TPB) sp[i] = gp[i];
        const float4* gf = (const float4*)(g_feat + (size_t)b * NWINT * 128);
        float4* sf = (float4*)(smem + SO_FEAT);
        for (int i = tid; i < NWINT * 8; i += TPB) sf[i] = gf[i];
    }
    __syncthreads();

    const int qp = wid & 3;
    const int js = wid >> 2;
    const int qA0 = qp * 32 + g;
    const int qA1 = qA0 + 8;
    const int qB0 = qA0 + 16;
    const int qB1 = qA0 + 24;

    const float tg = 2.0f * GG;
    u64 axA0, ayA0, azA0, ppA0, axA1, ayA1, azA1, ppA1;
    u64 axB0, ayB0, azB0, ppB0, axB1, ayB1, azB1, ppB1;
    {
        float4 y;
        y = g_y[src][b * NPTS + tile * 128 + qA0];
        axA0 = pk2(tg * y.x, tg * y.x); ayA0 = pk2(tg * y.y, tg * y.y);
        azA0 = pk2(tg * y.z, tg * y.z);
        float p = -GG * (y.x * y.x + y.y * y.y + y.z * y.z); ppA0 = pk2(p, p);
        y = g_y[src][b * NPTS + tile * 128 + qA1];
        axA1 = pk2(tg * y.x, tg * y.x); ayA1 = pk2(tg * y.y, tg * y.y);
        azA1 = pk2(tg * y.z, tg * y.z);
        p = -GG * (y.x * y.x + y.y * y.y + y.z * y.z); ppA1 = pk2(p, p);
        y = g_y[src][b * NPTS + tile * 128 + qB0];
        axB0 = pk2(tg * y.x, tg * y.x); ayB0 = pk2(tg * y.y, tg * y.y);
        azB0 = pk2(tg * y.z, tg * y.z);
        p = -GG * (y.x * y.x + y.y * y.y + y.z * y.z); ppB0 = pk2(p, p);
        y = g_y[src][b * NPTS + tile * 128 + qB1];
        axB1 = pk2(tg * y.x, tg * y.x); ayB1 = pk2(tg * y.y, tg * y.y);
        azB1 = pk2(tg * y.z, tg * y.z);
        p = -GG * (y.x * y.x + y.y * y.y + y.z * y.z); ppB1 = pk2(p, p);
    }

    // Poly-exp2 constants (minimax cubic on [-0.5,0.5], rel err ~8e-5).
    const u64 PC3 = pk2(0.05592080f, 0.05592080f);
    const u64 PC2 = pk2(0.24263100f, 0.24263100f);
    const u64 PC1 = pk2(0.69312119f, 0.69312119f);
    const u64 PC0 = pk2(0.99992486f, 0.99992486f);

    const bool ldb = (g < 4);
    const int gm = (g < 4) ? g : 3;

    float cA0 = 0.f, cA1 = 0.f, cA2 = 0.f, cA3 = 0.f;
    float cB0 = 0.f, cB1 = 0.f, cB2 = 0.f, cB3 = 0.f;

    u32 base = sb + (u32)(js * WINS_PER_JS) * 256u + 32u * (u32)t;
    u32 fb = sb + SO_FEAT + (u32)(js * WINS_PER_JS) * 128u + (u32)(gm * 32 + t * 4);

    #pragma unroll 2
    for (int w = 0; w < WINS_PER_JS; w++, base += 256u, fb += 128u) {
        u64 xx0, yy0, zz0, bb0, xx1, yy1, zz1, bb1;
        lds2(base, xx0, yy0);
        lds2(base + 16u, zz0, bb0);
        lds2(base + 128u, xx1, yy1);
        lds2(base + 144u, zz1, bb1);

        u64 tA00 = fma2(axA0, xx0, fma2(ayA0, yy0, fma2(azA0, zz0, add2(bb0, ppA0))));
        u64 tA10 = fma2(axA1, xx0, fma2(ayA1, yy0, fma2(azA1, zz0, add2(bb0, ppA1))));
        u64 tB00 = fma2(axB0, xx0, fma2(ayB0, yy0, fma2(azB0, zz0, add2(bb0, ppB0))));
        u64 tB10 = fma2(axB1, xx0, fma2(ayB1, yy0, fma2(azB1, zz0, add2(bb0, ppB1))));
        u64 tA01 = fma2(axA0, xx1, fma2(ayA0, yy1, fma2(azA0, zz1, add2(bb1, ppA0))));
        u64 tA11 = fma2(axA1, xx1, fma2(ayA1, yy1, fma2(azA1, zz1, add2(bb1, ppA1))));
        u64 tB01 = fma2(axB0, xx1, fma2(ayB0, yy1, fma2(azB0, zz1, add2(bb1, ppB0))));
        u64 tB11 = fma2(axB1, xx1, fma2(ayB1, yy1, fma2(azB1, zz1, add2(bb1, ppB1))));

        u32 f0 = lds32(fb);
        u32 f1 = lds32(fb + 16u);
        u32 b0 = ldb ? f0 : 0u;
        u32 b1 = ldb ? f1 : 0u;

        // 6 exps on MUFU, 2 on the FMA-pipe polynomial path.
        mma16816(cA0, cA1, cA2, cA3,
                 wgt2(tA00), wgt2(tA10), wgt2(tA01), wgt2(tA11), b0, b1);
        mma16816(cB0, cB1, cB2, cB3,
                 wgt2(tB00), wgt2p(tB10, PC3, PC2, PC1, PC0),
                 wgt2(tB01), wgt2p(tB11, PC3, PC2, PC1, PC0), b0, b1);
    }

    __syncthreads();   // points region is dead; psum overlays it

    float* ps = (float*)smem;
    if (t == 0) {
        ps[(js * 128 + qA0) * 4 + 0] = cA0; ps[(js * 128 + qA0) * 4 + 1] = cA1;
        ps[(js * 128 + qA1) * 4 + 0] = cA2; ps[(js * 128 + qA1) * 4 + 1] = cA3;
        ps[(js * 128 + qB0) * 4 + 0] = cB0; ps[(js * 128 + qB0) * 4 + 1] = cB1;
        ps[(js * 128 + qB1) * 4 + 0] = cB2; ps[(js * 128 + qB1) * 4 + 1] = cB3;
    } else if (t == 1) {
        ps[(js * 128 + qA0) * 4 + 2] = cA0; ps[(js * 128 + qA0) * 4 + 3] = cA1;
        ps[(js * 128 + qA1) * 4 + 2] = cA2; ps[(js * 128 + qA1) * 4 + 3] = cA3;
        ps[(js * 128 + qB0) * 4 + 2] = cB0; ps[(js * 128 + qB0) * 4 + 3] = cB1;
        ps[(js * 128 + qB1) * 4 + 2] = cB2; ps[(js * 128 + qB1) * 4 + 3] = cB3;
    }
    __syncthreads();

    if (tid < 128) {
        float4* pv = (float4*)smem;
        float4 a = pv[tid];
        #pragma unroll
        for (int k = 1; k < NJS; k++) {
            float4 s = pv[k * 128 + tid];
            a.x += s.x; a.y += s.y; a.z += s.z; a.w += s.w;
        }
        float inv = __fdividef(1.0f, a.w);
        float nx = a.x * inv, ny = a.y * inv, nz = a.z * inv;
        int qi = tile * 128 + tid;
        g_y[dst][b * NPTS + qi] = make_float4(nx, ny, nz, 0.f);
        if (out) {
            out[(b * 3 + 0) * NPTS + qi] = nx;
            out[(b * 3 + 1) * NPTS + qi] = ny;
            out[(b * 3 + 2) * NPTS + qi] = nz;
        }
    }
}

extern "C" void kernel_launch(void* const* d_in, const int* in_sizes, int n_in,
                              void* d_out, int out_size) {
    const float* x = (const float*)d_in[0];
    float* out = (float*)d_out;

    cudaFuncSetAttribute(iter_kernel, cudaFuncAttributeMaxDynamicSharedMemorySize, SMEMSZ);

    prep_kernel<<<(NB * NPTS + 255) / 256, 256>>>(x);

    dim3 grid(72, NB);
    for (int it = 0; it < 5; it++) {
        iter_kernel<<<grid, TPB, SMEMSZ>>>(it & 1, (it & 1) ^ 1, (it == 4) ? out : nullptr);
    }
}

// round 17
// speedup vs baseline: 1.9589x; 1.9589x over previous
#include <cuda_runtime.h>
#include <cuda_fp16.h>
#include <cstdint>

// MeanShift: B=2, C=3, N=9216, 5 iters.
// w_ij = exp2(arg), arg = 2g*y.x - g|y|^2 - g|x|^2, g = 50/ln2.
// R17: args computed by HMMA too. Split-precision rank-16 encoding:
//   A row (query) = [Ahx,Alx,Ahx, Ahy,Aly,Ahy, Ahz,Alz,Ahz, ph,pl, 1,1, 0,0,0]
//   B col (point) = [xhx,xhx,xlx, xhy,xhy,xly, xhz,xhz,xlz, 1,1, bnh,bnl, 0,0,0]
// One m16n8k16 (f32 accum) per 16q x 8pts gives args to ~1.5e-4 abs. The D
// fragment maps 1:1 onto the next MMA's A fragment after cvt+ex2 (FA trick).
// Mainloop per warp-window: 1 LDG.128 (static argB) + 4 arg-MMAs + 8 cvt/ex2
// + 2 acc-MMAs + 2 LDS feat. 768 thr = 4 query-pairs x 6 j-splits.

#define NPTS 9216
#define NB 2
#define GG 72.13475204444817f
#define TPB 768
#define NJS 6
#define WINS_PER_JS 96
#define NWINT 576

typedef unsigned long long u64;
typedef unsigned int u32;

__device__ float4 g_y[2][NB * NPTS];
__device__ __align__(16) unsigned char g_feat[NB * NWINT * 128];  // acc-B table
__device__ __align__(16) uint4 g_argB[NB * NWINT * 32];           // arg-B table

// smem: feat [0,73728) | Afrag stage [73728,77824) ; psum overlays [0,12288)
#define SO_STAGE 73728
#define SMEMSZ   77824

static __device__ __forceinline__ u32 pkh(__half a, __half b) {
    return (u32)__half_as_ushort(a) | ((u32)__half_as_ushort(b) << 16);
}
static __device__ __forceinline__ u32 lds32(u32 a) {
    u32 v; asm volatile("ld.shared.b32 %0,[%1];" : "=r"(v) : "r"(a)); return v;
}
static __device__ __forceinline__ void sts32(u32 a, u32 v) {
    asm volatile("st.shared.b32 [%0],%1;" :: "r"(a), "r"(v) : "memory");
}
// two f32 args (lo = k even, hi = k odd) -> fp16x2 weights.
static __device__ __forceinline__ u32 wgt2f(float lo, float hi) {
    u32 h;
    asm("{\n\tcvt.rn.f16x2.f32 %0,%2,%1;\n\tex2.approx.f16x2 %0,%0;\n\t}"
        : "=r"(h) : "f"(lo), "f"(hi));
    return h;
}
// arg MMA: D = A*B (zero C).
static __device__ __forceinline__ void mma_zc(
    float& d0, float& d1, float& d2, float& d3,
    u32 a0, u32 a1, u32 a2, u32 a3, u32 b0, u32 b1) {
    asm volatile("mma.sync.aligned.m16n8k16.row.col.f32.f16.f16.f32 "
        "{%0,%1,%2,%3}, {%4,%5,%6,%7}, {%8,%9}, {%10,%11,%12,%13};"
        : "=f"(d0), "=f"(d1), "=f"(d2), "=f"(d3)
        : "r"(a0), "r"(a1), "r"(a2), "r"(a3), "r"(b0), "r"(b1),
          "f"(0.0f), "f"(0.0f), "f"(0.0f), "f"(0.0f));
}
static __device__ __forceinline__ void mma16816(
    float& c0, float& c1, float& c2, float& c3,
    u32 a0, u32 a1, u32 a2, u32 a3, u32 b0, u32 b1) {
    asm volatile("mma.sync.aligned.m16n8k16.row.col.f32.f16.f16.f32 "
        "{%0,%1,%2,%3}, {%4,%5,%6,%7}, {%8,%9}, {%0,%1,%2,%3};"
        : "+f"(c0), "+f"(c1), "+f"(c2), "+f"(c3)
        : "r"(a0), "r"(a1), "r"(a2), "r"(a3), "r"(b0), "r"(b1));
}

__global__ void prep_kernel(const float* __restrict__ x) {
    int idx = blockIdx.x * blockDim.x + threadIdx.x;
    if (idx >= NB * NPTS) return;
    int b = idx / NPTS, n = idx - b * NPTS;
    float px = x[(b * 3 + 0) * NPTS + n];
    float py = x[(b * 3 + 1) * NPTS + n];
    float pz = x[(b * 3 + 2) * NPTS + n];
    g_y[0][b * NPTS + n] = make_float4(px, py, pz, 0.f);

    int w = n >> 4, i = n & 15;
    // acc-B feature table (unchanged from R14).
    unsigned char* fb = g_feat + ((size_t)(b * NWINT + w)) * 128
                      + (i >> 1) * 4 + (i & 1) * 2;
    *(__half*)(fb + 0)  = __float2half(px);
    *(__half*)(fb + 32) = __float2half(py);
    *(__half*)(fb + 64) = __float2half(pz);
    *(__half*)(fb + 96) = __float2half(1.0f);

    // arg-B table: K-slot values for this point.
    float bn = -GG * (px * px + py * py + pz * pz);
    __half xh = __float2half(px), yh = __float2half(py), zh = __float2half(pz);
    __half xl = __float2half(px - __half2float(xh));
    __half yl = __float2half(py - __half2float(yh));
    __half zl = __float2half(pz - __half2float(zh));
    __half bh = __float2half(bn);
    __half bl = __float2half(bn - __half2float(bh));
    __half on = __float2half(1.0f), ze = __float2half(0.0f);
    __half s[16] = {xh, xh, xl, yh, yh, yl, zh, zh, zl, on, on, bh, bl, ze, ze, ze};

    int g = i & 7;
    int hi = (i >> 3) & 1;   // 0: MMA-0 cols (pts 0-7), 1: MMA-1 (pts 8-15)
    u32* dst = (u32*)(g_argB + ((size_t)(b * NWINT + w)) * 32);
    #pragma unroll
    for (int t = 0; t < 4; t++) {
        u32 b0 = pkh(s[2 * t], s[2 * t + 1]);
        u32 b1 = pkh(s[2 * t + 8], s[2 * t + 9]);
        dst[(g * 4 + t) * 4 + (hi ? 2 : 0)] = b0;
        dst[(g * 4 + t) * 4 + (hi ? 3 : 1)] = b1;
    }
}

__global__ __launch_bounds__(TPB, 1) void iter_kernel(int src, int dst, float* __restrict__ out) {
    extern __shared__ __align__(16) unsigned char smem[];
    const int tid = threadIdx.x, wid = tid >> 5, lane = tid & 31;
    const int g = lane >> 2, t = lane & 3;
    const int b = blockIdx.y, tile = blockIdx.x;
    u32 sb = (u32)__cvta_generic_to_shared(smem);

    {   // stage acc-B feature table (73728 B)
        const float4* gf = (const float4*)(g_feat + (size_t)b * NWINT * 128);
        float4* sf = (float4*)smem;
        for (int i = tid; i < NWINT * 8; i += TPB) sf[i] = gf[i];
    }

    const int qp = wid & 3;
    const int js = wid >> 2;
    const int qA0 = qp * 32 + g;
    const int qA1 = qA0 + 8;
    const int qB0 = qA0 + 16;
    const int qB1 = qA0 + 24;

    // A-fragment staging: warps js==0, lanes t==0 write their 4 query rows.
    if (js == 0 && t == 0) {
        const float tg = 2.0f * GG;
        int rows[4] = {qA0, qA1, qB0, qB1};
        #pragma unroll
        for (int r = 0; r < 4; r++) {
            float4 y = g_y[src][b * NPTS + tile * 128 + rows[r]];
            float Ax = tg * y.x, Ay = tg * y.y, Az = tg * y.z;
            float p = -GG * (y.x * y.x + y.y * y.y + y.z * y.z);
            __half Axh = __float2half(Ax), Ayh = __float2half(Ay), Azh = __float2half(Az);
            __half Axl = __float2half(Ax - __half2float(Axh));
            __half Ayl = __float2half(Ay - __half2float(Ayh));
            __half Azl = __float2half(Az - __half2float(Azh));
            __half ph = __float2half(p);
            __half pl = __float2half(p - __half2float(ph));
            __half on = __float2half(1.0f), ze = __float2half(0.0f);
            u32 st = sb + SO_STAGE + (u32)(rows[r] * 32);
            sts32(st + 0,  pkh(Axh, Axl));
            sts32(st + 4,  pkh(Axh, Ayh));
            sts32(st + 8,  pkh(Ayl, Ayh));
            sts32(st + 12, pkh(Azh, Azl));
            sts32(st + 16, pkh(Azh, ph));
            sts32(st + 20, pkh(pl, on));
            sts32(st + 24, pkh(on, ze));
            sts32(st + 28, 0u);
        }
    }
    __syncthreads();

    // Read A fragments (conflict-free: 32 distinct banks).
    u32 stg = sb + SO_STAGE;
    u32 aA0 = lds32(stg + (u32)(qA0 * 32 + t * 4));
    u32 aA1 = lds32(stg + (u32)(qA1 * 32 + t * 4));
    u32 aA2 = lds32(stg + (u32)(qA0 * 32 + 16 + t * 4));
    u32 aA3 = lds32(stg + (u32)(qA1 * 32 + 16 + t * 4));
    u32 aB0 = lds32(stg + (u32)(qB0 * 32 + t * 4));
    u32 aB1 = lds32(stg + (u32)(qB1 * 32 + t * 4));
    u32 aB2 = lds32(stg + (u32)(qB0 * 32 + 16 + t * 4));
    u32 aB3 = lds32(stg + (u32)(qB1 * 32 + 16 + t * 4));

    const bool ldb = (g < 4);
    const int gm = (g < 4) ? g : 3;

    float cA0 = 0.f, cA1 = 0.f, cA2 = 0.f, cA3 = 0.f;
    float cB0 = 0.f, cB1 = 0.f, cB2 = 0.f, cB3 = 0.f;

    const uint4* __restrict__ ab = g_argB + (size_t)(b * NWINT + js * WINS_PER_JS) * 32 + lane;
    u32 fbp = sb + (u32)(js * WINS_PER_JS) * 128u + (u32)(gm * 32 + t * 4);

    uint4 bb = *ab; ab += 32;    // prefetched window 0

    for (int w = 0; w < WINS_PER_JS; w++, fbp += 128u) {
        uint4 cur = bb;
        if (w + 1 < WINS_PER_JS) { bb = *ab; ab += 32; }   // prefetch next

        // arg MMAs: qA rows x pts0-7, pts8-15; qB rows likewise.
        float d0, d1, d2, d3, e0, e1, e2, e3;
        mma_zc(d0, d1, d2, d3, aA0, aA1, aA2, aA3, cur.x, cur.y);
        mma_zc(e0, e1, e2, e3, aA0, aA1, aA2, aA3, cur.z, cur.w);
        u32 wA0 = wgt2f(d0, d1);     // row g,   pts 2t,2t+1
        u32 wA1 = wgt2f(d2, d3);     // row g+8, pts 2t,2t+1
        u32 wA2 = wgt2f(e0, e1);     // row g,   pts 8+2t,8+2t+1
        u32 wA3 = wgt2f(e2, e3);

        float f0_, f1_, f2_, f3_, h0, h1, h2, h3;
        mma_zc(f0_, f1_, f2_, f3_, aB0, aB1, aB2, aB3, cur.x, cur.y);
        mma_zc(h0, h1, h2, h3, aB0, aB1, aB2, aB3, cur.z, cur.w);
        u32 wB0 = wgt2f(f0_, f1_);
        u32 wB1 = wgt2f(f2_, f3_);
        u32 wB2 = wgt2f(h0, h1);
        u32 wB3 = wgt2f(h2, h3);

        u32 f0 = lds32(fbp);
        u32 f1 = lds32(fbp + 16u);
        u32 b0 = ldb ? f0 : 0u;
        u32 b1 = ldb ? f1 : 0u;

        mma16816(cA0, cA1, cA2, cA3, wA0, wA1, wA2, wA3, b0, b1);
        mma16816(cB0, cB1, cB2, cB3, wB0, wB1, wB2, wB3, b0, b1);
    }

    __syncthreads();   // feat region is dead; psum overlays it

    float* ps = (float*)smem;
    if (t == 0) {
        ps[(js * 128 + qA0) * 4 + 0] = cA0; ps[(js * 128 + qA0) * 4 + 1] = cA1;
        ps[(js * 128 + qA1) * 4 + 0] = cA2; ps[(js * 128 + qA1) * 4 + 1] = cA3;
        ps[(js * 128 + qB0) * 4 + 0] = cB0; ps[(js * 128 + qB0) * 4 + 1] = cB1;
        ps[(js * 128 + qB1) * 4 + 0] = cB2; ps[(js * 128 + qB1) * 4 + 1] = cB3;
    } else if (t == 1) {
        ps[(js * 128 + qA0) * 4 + 2] = cA0; ps[(js * 128 + qA0) * 4 + 3] = cA1;
        ps[(js * 128 + qA1) * 4 + 2] = cA2; ps[(js * 128 + qA1) * 4 + 3] = cA3;
        ps[(js * 128 + qB0) * 4 + 2] = cB0; ps[(js * 128 + qB0) * 4 + 3] = cB1;
        ps[(js * 128 + qB1) * 4 + 2] = cB2; ps[(js * 128 + qB1) * 4 + 3] = cB3;
    }
    __syncthreads();

    if (tid < 128) {
        float4* pv = (float4*)smem;
        float4 a = pv[tid];
        #pragma unroll
        for (int k = 1; k < NJS; k++) {
            float4 s = pv[k * 128 + tid];
            a.x += s.x; a.y += s.y; a.z += s.z; a.w += s.w;
        }
        float inv = __fdividef(1.0f, a.w);
        float nx = a.x * inv, ny = a.y * inv, nz = a.z * inv;
        int qi = tile * 128 + tid;
        g_y[dst][b * NPTS + qi] = make_float4(nx, ny, nz, 0.f);
        if (out) {
            out[(b * 3 + 0) * NPTS + qi] = nx;
            out[(b * 3 + 1) * NPTS + qi] = ny;
            out[(b * 3 + 2) * NPTS + qi] = nz;
        }
    }
}

extern "C" void kernel_launch(void* const* d_in, const int* in_sizes, int n_in,
                              void* d_out, int out_size) {
    const float* x = (const float*)d_in[0];
    float* out = (float*)d_out;

    cudaFuncSetAttribute(iter_kernel, cudaFuncAttributeMaxDynamicSharedMemorySize, SMEMSZ);

    prep_kernel<<<(NB * NPTS + 255) / 256, 256>>>(x);

    dim3 grid(72, NB);
    for (int it = 0; it < 5; it++) {
        iter_kernel<<<grid, TPB, SMEMSZ>>>(it & 1, (it & 1) ^ 1, (it == 4) ? out : nullptr);
    }
}